// round 1
// baseline (speedup 1.0000x reference)
#include <cuda_runtime.h>
#include <cuda_fp16.h>

#define NB 256
#define NN 512
#define EPSV 1e-10f

// ---- scratch (device globals; no allocation allowed) ----
__device__ uint4  d_Mraw[(size_t)NB * NN * NN / 8];   // 128 MB fp16 matrix storage
__device__ float  d_t[NB * NN];
__device__ float  d_g[NB * NN];
__device__ float  d_idcg[NB];
__device__ float  d_ndcg[NB];

// ------------------------------------------------------------------
// Kernel 1: per-batch stats: t_c = sum_k |s_c - s_k|, gains g, idcg
// ------------------------------------------------------------------
__global__ __launch_bounds__(NN) void stats_kernel(const float* __restrict__ y_pred,
                                                   const float* __restrict__ y_true) {
    __shared__ float sp[NN];
    __shared__ float sy[NN];
    __shared__ float red[16];
    int b = blockIdx.x, tid = threadIdx.x;
    sp[tid] = y_pred[b * NN + tid];
    sy[tid] = y_true[b * NN + tid];
    __syncthreads();

    // t_c with Kahan compensation (512 terms, sum ~500)
    float sc = sp[tid];
    float acc = 0.f, comp = 0.f;
    #pragma unroll 8
    for (int k = 0; k < NN; k++) {
        float term = fabsf(sc - sp[k]) - comp;
        float ns = acc + term;
        comp = (ns - acc) - term;
        acc = ns;
    }
    d_t[b * NN + tid] = acc;

    float yv = sy[tid];
    float g = exp2f(yv) - 1.f;
    d_g[b * NN + tid] = g;

    // stable-descending rank; ties don't change idcg value
    int rank = 0;
    #pragma unroll 8
    for (int k = 0; k < NN; k++) {
        float o = sy[k];
        rank += (o > yv) || (o == yv && k < tid);
    }
    float contrib = g / log2f((float)(rank + 2));
    for (int off = 16; off; off >>= 1)
        contrib += __shfl_xor_sync(0xffffffffu, contrib, off);
    if ((tid & 31) == 0) red[tid >> 5] = contrib;
    __syncthreads();
    if (tid == 0) {
        float s = 0.f;
        for (int w = 0; w < 16; w++) s += red[w];
        d_idcg[b] = s;
    }
}

// ------------------------------------------------------------------
// Kernel 2: build M (NeuralSort softmax rows), one warp per row.
// M[r][c] = softmax_c( (n-1-2r)*s_c - t_c ), stored fp16.
// Column layout per lane: cols {2*lane + 64k}, fully coalesced.
// ------------------------------------------------------------------
__global__ __launch_bounds__(256) void build_kernel(const float* __restrict__ y_pred) {
    int wid = threadIdx.x >> 5, lane = threadIdx.x & 31;
    int rg = blockIdx.x * 8 + wid;          // global row 0..NB*NN-1
    int b = rg >> 9, r = rg & (NN - 1);
    const float* s  = y_pred + b * NN;
    const float* tt = d_t + b * NN;
    float a = (float)(NN - 1 - 2 * r);

    float lg[16];
    float mx = -3.4e38f;
    #pragma unroll
    for (int k = 0; k < 8; k++) {
        int c = 2 * lane + 64 * k;
        float2 sv = *(const float2*)(s + c);
        float2 tv = *(const float2*)(tt + c);
        lg[2 * k]     = a * sv.x - tv.x;
        lg[2 * k + 1] = a * sv.y - tv.y;
        mx = fmaxf(mx, fmaxf(lg[2 * k], lg[2 * k + 1]));
    }
    for (int off = 16; off; off >>= 1)
        mx = fmaxf(mx, __shfl_xor_sync(0xffffffffu, mx, off));
    float sum = 0.f;
    #pragma unroll
    for (int i = 0; i < 16; i++) { lg[i] = __expf(lg[i] - mx); sum += lg[i]; }
    for (int off = 16; off; off >>= 1)
        sum += __shfl_xor_sync(0xffffffffu, sum, off);
    float inv = 1.f / sum;

    __half2* out = (__half2*)d_Mraw + (size_t)rg * (NN / 2) + lane;
    #pragma unroll
    for (int k = 0; k < 8; k++)
        out[32 * k] = __floats2half2_rn(lg[2 * k] * inv, lg[2 * k + 1] * inv);
}

// ------------------------------------------------------------------
// Kernel 3: Sinkhorn via scale vectors u,v. One CTA per batch.
// Per iteration only ONE streaming pass over M: row-scan computes
// r_i = M v (dot), updates u_i, and immediately accumulates the NEXT
// iteration's q_j = sum_i M_ij u_i from the registers already loaded.
// Final (50th) pass also computes ground_truth and ndcg.
// ------------------------------------------------------------------
__global__ __launch_bounds__(NN) void sinkhorn_kernel() {
    __shared__ float sh_u[NN], sh_v[NN], sh_q[NN], sh_w[NN];
    __shared__ float sh_qpart[16][NN];
    __shared__ float sh_red[16];

    int b = blockIdx.x, tid = threadIdx.x, wid = tid >> 5, lane = tid & 31;
    const __half2* Mb = (const __half2*)d_Mraw + (size_t)b * NN * (NN / 2);

    sh_u[tid] = 1.f;
    sh_v[tid] = 1.f;
    __syncthreads();

    // ---- pass 0: q = column sums of M (u = 1) ----
    {
        float qacc[16];
        #pragma unroll
        for (int i = 0; i < 16; i++) qacc[i] = 0.f;
        for (int it = 0; it < 32; it++) {
            int row = wid + it * 16;
            const __half2* rp = Mb + row * (NN / 2) + lane;
            #pragma unroll
            for (int k = 0; k < 8; k++) {
                float2 f = __half22float2(rp[32 * k]);
                qacc[2 * k]     += f.x;
                qacc[2 * k + 1] += f.y;
            }
        }
        #pragma unroll
        for (int k = 0; k < 8; k++)
            *(float2*)&sh_qpart[wid][2 * lane + 64 * k] =
                make_float2(qacc[2 * k], qacc[2 * k + 1]);
        __syncthreads();
        float s = 0.f;
        #pragma unroll
        for (int w = 0; w < 16; w++) s += sh_qpart[w][tid];
        sh_q[tid] = s;
        __syncthreads();
    }

    for (int t = 1; t <= 50; t++) {
        // column step: v_j <- v_j / max(v_j * q_j, EPS)
        float vv = sh_v[tid];
        vv = vv / fmaxf(vv * sh_q[tid], EPSV);
        sh_v[tid] = vv;
        if (t == 50) sh_w[tid] = vv * d_g[b * NN + tid];
        __syncthreads();

        float vreg[16];
        #pragma unroll
        for (int k = 0; k < 8; k++) {
            float2 f = *(const float2*)&sh_v[2 * lane + 64 * k];
            vreg[2 * k] = f.x; vreg[2 * k + 1] = f.y;
        }

        if (t < 50) {
            float qacc[16];
            #pragma unroll
            for (int i = 0; i < 16; i++) qacc[i] = 0.f;

            __half2 buf[8];
            {
                const __half2* rp = Mb + wid * (NN / 2) + lane;
                #pragma unroll
                for (int k = 0; k < 8; k++) buf[k] = rp[32 * k];
            }
            for (int it = 0; it < 32; it++) {
                int row = wid + it * 16;
                __half2 cur[8];
                #pragma unroll
                for (int k = 0; k < 8; k++) cur[k] = buf[k];
                if (it < 31) {
                    const __half2* rp = Mb + (row + 16) * (NN / 2) + lane;
                    #pragma unroll
                    for (int k = 0; k < 8; k++) buf[k] = rp[32 * k];
                }
                float2 f[8];
                float dot = 0.f;
                #pragma unroll
                for (int k = 0; k < 8; k++) {
                    f[k] = __half22float2(cur[k]);
                    dot += f[k].x * vreg[2 * k] + f[k].y * vreg[2 * k + 1];
                }
                #pragma unroll
                for (int off = 16; off; off >>= 1)
                    dot += __shfl_xor_sync(0xffffffffu, dot, off);
                float un = 0.f;
                if (lane == 0) {
                    float uo = sh_u[row];
                    un = uo / fmaxf(uo * dot, EPSV);
                    sh_u[row] = un;
                }
                un = __shfl_sync(0xffffffffu, un, 0);
                #pragma unroll
                for (int k = 0; k < 8; k++) {
                    qacc[2 * k]     += un * f[k].x;
                    qacc[2 * k + 1] += un * f[k].y;
                }
            }
            #pragma unroll
            for (int k = 0; k < 8; k++)
                *(float2*)&sh_qpart[wid][2 * lane + 64 * k] =
                    make_float2(qacc[2 * k], qacc[2 * k + 1]);
            __syncthreads();
            float s = 0.f;
            #pragma unroll
            for (int w = 0; w < 16; w++) s += sh_qpart[w][tid];
            sh_q[tid] = s;
            __syncthreads();
        } else {
            // final pass: finish row step and compute ndcg directly
            float wacc = 0.f;
            for (int it = 0; it < 32; it++) {
                int row = wid + it * 16;
                const __half2* rp = Mb + row * (NN / 2) + lane;
                float dot = 0.f, dw = 0.f;
                #pragma unroll
                for (int k = 0; k < 8; k++) {
                    float2 f  = __half22float2(rp[32 * k]);
                    float2 vw = *(const float2*)&sh_w[2 * lane + 64 * k];
                    dot += f.x * vreg[2 * k] + f.y * vreg[2 * k + 1];
                    dw  += f.x * vw.x + f.y * vw.y;
                }
                #pragma unroll
                for (int off = 16; off; off >>= 1) {
                    dot += __shfl_xor_sync(0xffffffffu, dot, off);
                    dw  += __shfl_xor_sync(0xffffffffu, dw, off);
                }
                if (lane == 0) {
                    float uo = sh_u[row];
                    float un = uo / fmaxf(uo * dot, EPSV);
                    float disc = 1.f / log2f((float)(row + 2));
                    wacc += disc * un * dw;
                }
            }
            if (lane == 0) sh_red[wid] = wacc;
            __syncthreads();
            if (tid == 0) {
                float s = 0.f;
                for (int w = 0; w < 16; w++) s += sh_red[w];
                float idcg = d_idcg[b];
                d_ndcg[b] = (idcg == 0.f) ? 0.f : s / (idcg + EPSV);
            }
        }
    }
}

// ------------------------------------------------------------------
// Kernel 4: deterministic final reduction: loss = -sum(ndcg)/count
// ------------------------------------------------------------------
__global__ __launch_bounds__(NB) void finalize_kernel(float* __restrict__ out) {
    __shared__ float sred[8];
    __shared__ int   cred[8];
    int tid = threadIdx.x;
    float nd = d_ndcg[tid];
    int nz = (d_idcg[tid] != 0.f) ? 1 : 0;
    for (int off = 16; off; off >>= 1) {
        nd += __shfl_xor_sync(0xffffffffu, nd, off);
        nz += __shfl_xor_sync(0xffffffffu, nz, off);
    }
    if ((tid & 31) == 0) { sred[tid >> 5] = nd; cred[tid >> 5] = nz; }
    __syncthreads();
    if (tid == 0) {
        float s = 0.f; int c = 0;
        for (int w = 0; w < 8; w++) { s += sred[w]; c += cred[w]; }
        out[0] = (c > 0) ? (-s / (float)c) : 0.f;
    }
}

extern "C" void kernel_launch(void* const* d_in, const int* in_sizes, int n_in,
                              void* d_out, int out_size) {
    const float* y_pred = (const float*)d_in[0];
    const float* y_true = (const float*)d_in[1];
    float* out = (float*)d_out;

    stats_kernel<<<NB, NN>>>(y_pred, y_true);
    build_kernel<<<NB * NN / 8, 256>>>(y_pred);
    sinkhorn_kernel<<<NB, NN>>>();
    finalize_kernel<<<1, NB>>>(out);
}

// round 4
// speedup vs baseline: 2.1694x; 2.1694x over previous
#include <cuda_runtime.h>
#include <cuda_fp16.h>
#include <cuda_fp8.h>

#define NB 256
#define NN 512
#define EPSV 1e-10f
#define MSCALE 256.0f
#define FULLMASK 0xffffffffu

// ---- scratch (device globals; no allocation allowed) ----
__device__ uint4 d_M8[(size_t)NB * NN * (NN / 16)];   // 64 MB fp8 e4m3, scaled by 256
__device__ float d_t[NB * NN];
__device__ float d_g[NB * NN];
__device__ float d_idcg[NB];
__device__ float d_ndcg[NB];

// ---- fp8 helpers (cuda_fp8.h intrinsics only; no inline asm) ----
__device__ __forceinline__ unsigned enc4(float f0, float f1, float f2, float f3) {
    __nv_fp8x2_storage_t lo =
        __nv_cvt_float2_to_fp8x2(make_float2(f0, f1), __NV_SATFINITE, __NV_E4M3);
    __nv_fp8x2_storage_t hi =
        __nv_cvt_float2_to_fp8x2(make_float2(f2, f3), __NV_SATFINITE, __NV_E4M3);
    return (unsigned)lo | ((unsigned)hi << 16);
}
__device__ __forceinline__ void dec4(unsigned w, __half2& h0, __half2& h1) {
    h0 = __half2(__nv_cvt_fp8x2_to_halfraw2((__nv_fp8x2_storage_t)(w & 0xffffu), __NV_E4M3));
    h1 = __half2(__nv_cvt_fp8x2_to_halfraw2((__nv_fp8x2_storage_t)(w >> 16), __NV_E4M3));
}

// ------------------------------------------------------------------
// Kernel 1: per-batch stats: t_c = sum_k |s_c - s_k|, gains g, idcg
// ------------------------------------------------------------------
__global__ __launch_bounds__(NN) void stats_kernel(const float* __restrict__ y_pred,
                                                   const float* __restrict__ y_true) {
    __shared__ float sp[NN];
    __shared__ float sy[NN];
    __shared__ float red[16];
    int b = blockIdx.x, tid = threadIdx.x;
    sp[tid] = y_pred[b * NN + tid];
    sy[tid] = y_true[b * NN + tid];
    __syncthreads();

    float sc = sp[tid];
    float acc = 0.f, comp = 0.f;
    #pragma unroll 8
    for (int k = 0; k < NN; k++) {
        float term = fabsf(sc - sp[k]) - comp;
        float ns = acc + term;
        comp = (ns - acc) - term;
        acc = ns;
    }
    d_t[b * NN + tid] = acc;

    float yv = sy[tid];
    float g = exp2f(yv) - 1.f;
    d_g[b * NN + tid] = g;

    int rank = 0;
    #pragma unroll 8
    for (int k = 0; k < NN; k++) {
        float o = sy[k];
        rank += (o > yv) || (o == yv && k < tid);
    }
    float contrib = g / log2f((float)(rank + 2));
    for (int off = 16; off; off >>= 1)
        contrib += __shfl_xor_sync(FULLMASK, contrib, off);
    if ((tid & 31) == 0) red[tid >> 5] = contrib;
    __syncthreads();
    if (tid == 0) {
        float s = 0.f;
        for (int w = 0; w < 16; w++) s += red[w];
        d_idcg[b] = s;
    }
}

// ------------------------------------------------------------------
// Kernel 2: build M' = 256 * softmax_row, fp8 e4m3, one warp per row.
// Lane L covers contiguous cols [16L, 16L+16) -> one uint4 store.
// ------------------------------------------------------------------
__global__ __launch_bounds__(256) void build_kernel(const float* __restrict__ y_pred) {
    int wid = threadIdx.x >> 5, lane = threadIdx.x & 31;
    int rg = blockIdx.x * 8 + wid;
    int b = rg >> 9, r = rg & (NN - 1);
    const float4* s4 = (const float4*)(y_pred + b * NN + 16 * lane);
    const float4* t4 = (const float4*)(d_t + b * NN + 16 * lane);
    float a = (float)(NN - 1 - 2 * r);

    float lg[16];
    float mx = -3.4e38f;
    #pragma unroll
    for (int k = 0; k < 4; k++) {
        float4 sv = s4[k], tv = t4[k];
        lg[4 * k + 0] = a * sv.x - tv.x;
        lg[4 * k + 1] = a * sv.y - tv.y;
        lg[4 * k + 2] = a * sv.z - tv.z;
        lg[4 * k + 3] = a * sv.w - tv.w;
        mx = fmaxf(mx, fmaxf(fmaxf(lg[4 * k], lg[4 * k + 1]), fmaxf(lg[4 * k + 2], lg[4 * k + 3])));
    }
    #pragma unroll
    for (int off = 16; off; off >>= 1)
        mx = fmaxf(mx, __shfl_xor_sync(FULLMASK, mx, off));
    float sum = 0.f;
    #pragma unroll
    for (int i = 0; i < 16; i++) { lg[i] = __expf(lg[i] - mx); sum += lg[i]; }
    #pragma unroll
    for (int off = 16; off; off >>= 1)
        sum += __shfl_xor_sync(FULLMASK, sum, off);
    float sc = MSCALE / sum;

    uint4 out;
    out.x = enc4(lg[0] * sc, lg[1] * sc, lg[2] * sc, lg[3] * sc);
    out.y = enc4(lg[4] * sc, lg[5] * sc, lg[6] * sc, lg[7] * sc);
    out.z = enc4(lg[8] * sc, lg[9] * sc, lg[10] * sc, lg[11] * sc);
    out.w = enc4(lg[12] * sc, lg[13] * sc, lg[14] * sc, lg[15] * sc);
    d_M8[(size_t)rg * 32 + lane] = out;
}

// ------------------------------------------------------------------
// Kernel 3: Sinkhorn on fp8 M, L2-resident. One CTA per batch.
// u kept in registers (pair p owned by lane p); v staged as half2;
// conflict-free half2 smem staging for q partials.
// ------------------------------------------------------------------
__global__ __launch_bounds__(NN) void sinkhorn_kernel() {
    __shared__ __align__(16) __half2 sh_vh[NN / 2];
    __shared__ __align__(16) __half2 sh_wh[NN / 2];
    __shared__ __align__(16) __half2 sh_qph[16][NN / 2];
    __shared__ float sh_q[NN];
    __shared__ float sh_red[16];

    int b = blockIdx.x, tid = threadIdx.x, wid = tid >> 5, lane = tid & 31;
    const uint4* Mb = d_M8 + (size_t)b * NN * 32;

    float uA = 1.f, uB = 1.f;   // u for rows wid+32*p, wid+32*p+16 (owned by lane p)
    float vv = 1.f;             // v for column tid

    // ---- pass 0: column sums (u = 1) ----
    {
        __half2 qh[8];
        #pragma unroll
        for (int k = 0; k < 8; k++) qh[k] = __float2half2_rn(0.f);
        uint4 buf = Mb[wid * 32 + lane];
        for (int it = 0; it < 32; it++) {
            uint4 cur = buf;
            if (it < 31) buf = Mb[(wid + 16 * (it + 1)) * 32 + lane];
            __half2 h[8];
            dec4(cur.x, h[0], h[1]); dec4(cur.y, h[2], h[3]);
            dec4(cur.z, h[4], h[5]); dec4(cur.w, h[6], h[7]);
            #pragma unroll
            for (int k = 0; k < 8; k++) qh[k] = __hadd2(qh[k], h[k]);
        }
        *(uint4*)&sh_qph[wid][8 * lane]     = *(uint4*)&qh[0];
        *(uint4*)&sh_qph[wid][8 * lane + 4] = *(uint4*)&qh[4];
        __syncthreads();
        float s = 0.f;
        #pragma unroll
        for (int w = 0; w < 16; w++) {
            float2 f = __half22float2(sh_qph[w][tid >> 1]);
            s += (tid & 1) ? f.y : f.x;
        }
        sh_q[tid] = s;
    }

    for (int t = 1; t <= 50; t++) {
        // column step: v_j <- v_j / max(v_j * q_j, EPS)
        vv = __fdividef(vv, fmaxf(vv * sh_q[tid], EPSV));
        float vnext = __shfl_down_sync(FULLMASK, vv, 1);
        if ((lane & 1) == 0) sh_vh[tid >> 1] = __floats2half2_rn(vv, vnext);
        if (t == 50) {
            float wv = vv * d_g[b * NN + tid];
            float wnext = __shfl_down_sync(FULLMASK, wv, 1);
            if ((lane & 1) == 0) sh_wh[tid >> 1] = __floats2half2_rn(wv, wnext);
        }
        __syncthreads();

        __half2 vh[8];
        *(uint4*)&vh[0] = *(const uint4*)&sh_vh[8 * lane];
        *(uint4*)&vh[4] = *(const uint4*)&sh_vh[8 * lane + 4];

        if (t < 50) {
            __half2 qh[8];
            #pragma unroll
            for (int k = 0; k < 8; k++) qh[k] = __float2half2_rn(0.f);
            uint4 bA = Mb[wid * 32 + lane];
            uint4 bB = Mb[(wid + 16) * 32 + lane];
            #pragma unroll 2
            for (int p = 0; p < 16; p++) {
                uint4 cA = bA, cB = bB;
                if (p < 15) {
                    int r2 = wid + 32 * (p + 1);
                    bA = Mb[r2 * 32 + lane];
                    bB = Mb[(r2 + 16) * 32 + lane];
                }
                __half2 ha[8], hb[8];
                dec4(cA.x, ha[0], ha[1]); dec4(cA.y, ha[2], ha[3]);
                dec4(cA.z, ha[4], ha[5]); dec4(cA.w, ha[6], ha[7]);
                dec4(cB.x, hb[0], hb[1]); dec4(cB.y, hb[2], hb[3]);
                dec4(cB.z, hb[4], hb[5]); dec4(cB.w, hb[6], hb[7]);
                __half2 dA = __float2half2_rn(0.f), dB = dA;
                #pragma unroll
                for (int k = 0; k < 8; k++) {
                    dA = __hfma2(ha[k], vh[k], dA);
                    dB = __hfma2(hb[k], vh[k], dB);
                }
                dA = __hadd2(dA, __lowhigh2highlow(dA));
                dB = __hadd2(dB, __lowhigh2highlow(dB));
                __half2 dp = __halves2half2(__low2half(dA), __low2half(dB));
                #pragma unroll
                for (int off = 16; off; off >>= 1) {
                    unsigned x = __shfl_xor_sync(FULLMASK, *(unsigned*)&dp, off);
                    dp = __hadd2(dp, *(__half2*)&x);
                }
                float2 dots = __half22float2(dp);
                float uoA = __shfl_sync(FULLMASK, uA, p);
                float uoB = __shfl_sync(FULLMASK, uB, p);
                float unA = __fdividef(uoA, fmaxf(uoA * dots.x, EPSV));
                float unB = __fdividef(uoB, fmaxf(uoB * dots.y, EPSV));
                if (lane == p) { uA = unA; uB = unB; }
                __half2 a2 = __float2half2_rn(unA), b2 = __float2half2_rn(unB);
                #pragma unroll
                for (int k = 0; k < 8; k++) {
                    qh[k] = __hfma2(ha[k], a2, qh[k]);
                    qh[k] = __hfma2(hb[k], b2, qh[k]);
                }
            }
            *(uint4*)&sh_qph[wid][8 * lane]     = *(uint4*)&qh[0];
            *(uint4*)&sh_qph[wid][8 * lane + 4] = *(uint4*)&qh[4];
            __syncthreads();
            float s = 0.f;
            #pragma unroll
            for (int w = 0; w < 16; w++) {
                float2 f = __half22float2(sh_qph[w][tid >> 1]);
                s += (tid & 1) ? f.y : f.x;
            }
            sh_q[tid] = s;
        } else {
            // final pass: finish row step + ndcg
            __half2 wh[8];
            *(uint4*)&wh[0] = *(const uint4*)&sh_wh[8 * lane];
            *(uint4*)&wh[4] = *(const uint4*)&sh_wh[8 * lane + 4];
            float wacc = 0.f;
            uint4 bA = Mb[wid * 32 + lane];
            uint4 bB = Mb[(wid + 16) * 32 + lane];
            #pragma unroll 2
            for (int p = 0; p < 16; p++) {
                uint4 cA = bA, cB = bB;
                if (p < 15) {
                    int r2 = wid + 32 * (p + 1);
                    bA = Mb[r2 * 32 + lane];
                    bB = Mb[(r2 + 16) * 32 + lane];
                }
                __half2 ha[8], hb[8];
                dec4(cA.x, ha[0], ha[1]); dec4(cA.y, ha[2], ha[3]);
                dec4(cA.z, ha[4], ha[5]); dec4(cA.w, ha[6], ha[7]);
                dec4(cB.x, hb[0], hb[1]); dec4(cB.y, hb[2], hb[3]);
                dec4(cB.z, hb[4], hb[5]); dec4(cB.w, hb[6], hb[7]);
                __half2 dA = __float2half2_rn(0.f), dB = dA, eA = dA, eB = dA;
                #pragma unroll
                for (int k = 0; k < 8; k++) {
                    dA = __hfma2(ha[k], vh[k], dA);
                    dB = __hfma2(hb[k], vh[k], dB);
                    eA = __hfma2(ha[k], wh[k], eA);
                    eB = __hfma2(hb[k], wh[k], eB);
                }
                dA = __hadd2(dA, __lowhigh2highlow(dA));
                dB = __hadd2(dB, __lowhigh2highlow(dB));
                eA = __hadd2(eA, __lowhigh2highlow(eA));
                eB = __hadd2(eB, __lowhigh2highlow(eB));
                __half2 dp = __halves2half2(__low2half(dA), __low2half(dB));
                __half2 ep = __halves2half2(__low2half(eA), __low2half(eB));
                #pragma unroll
                for (int off = 16; off; off >>= 1) {
                    unsigned x = __shfl_xor_sync(FULLMASK, *(unsigned*)&dp, off);
                    unsigned y = __shfl_xor_sync(FULLMASK, *(unsigned*)&ep, off);
                    dp = __hadd2(dp, *(__half2*)&x);
                    ep = __hadd2(ep, *(__half2*)&y);
                }
                float2 dots = __half22float2(dp);
                float2 es = __half22float2(ep);
                float uoA = __shfl_sync(FULLMASK, uA, p);
                float uoB = __shfl_sync(FULLMASK, uB, p);
                float unA = __fdividef(uoA, fmaxf(uoA * dots.x, EPSV));
                float unB = __fdividef(uoB, fmaxf(uoB * dots.y, EPSV));
                int rowA = wid + 32 * p;
                float discA = __fdividef(1.f, log2f((float)(rowA + 2)));
                float discB = __fdividef(1.f, log2f((float)(rowA + 18)));
                wacc += discA * unA * es.x + discB * unB * es.y;
            }
            if (lane == 0) sh_red[wid] = wacc;
            __syncthreads();
            if (tid == 0) {
                float s = 0.f;
                for (int w = 0; w < 16; w++) s += sh_red[w];
                float idcg = d_idcg[b];
                d_ndcg[b] = (idcg == 0.f) ? 0.f : s / (idcg + EPSV);
            }
        }
    }
}

// ------------------------------------------------------------------
// Kernel 4: final reduction: loss = -sum(ndcg)/count
// ------------------------------------------------------------------
__global__ __launch_bounds__(NB) void finalize_kernel(float* __restrict__ out) {
    __shared__ float sred[8];
    __shared__ int cred[8];
    int tid = threadIdx.x;
    float nd = d_ndcg[tid];
    int nz = (d_idcg[tid] != 0.f) ? 1 : 0;
    for (int off = 16; off; off >>= 1) {
        nd += __shfl_xor_sync(FULLMASK, nd, off);
        nz += __shfl_xor_sync(FULLMASK, nz, off);
    }
    if ((tid & 31) == 0) { sred[tid >> 5] = nd; cred[tid >> 5] = nz; }
    __syncthreads();
    if (tid == 0) {
        float s = 0.f; int c = 0;
        for (int w = 0; w < 8; w++) { s += sred[w]; c += cred[w]; }
        out[0] = (c > 0) ? (-s / (float)c) : 0.f;
    }
}

extern "C" void kernel_launch(void* const* d_in, const int* in_sizes, int n_in,
                              void* d_out, int out_size) {
    const float* y_pred = (const float*)d_in[0];
    const float* y_true = (const float*)d_in[1];
    float* out = (float*)d_out;

    stats_kernel<<<NB, NN>>>(y_pred, y_true);
    build_kernel<<<NB * NN / 8, 256>>>(y_pred);
    sinkhorn_kernel<<<NB, NN>>>();
    finalize_kernel<<<1, NB>>>(out);
}